// round 7
// baseline (speedup 1.0000x reference)
#include <cuda_runtime.h>
#include <cuda_bf16.h>
#include <cstdint>

#define N_NODES 100000
#define N_EDGES 1600000
#define IN_DIM  128
#define HID     256
#define OUT_DIM 128

// ---------------- scratch (no allocations allowed) ----------------
static __device__ float  g_aggr[(size_t)N_NODES * IN_DIM];   // 51.2 MB
static __device__ float  g_h1[(size_t)N_NODES * HID];        // 102.4 MB
static __device__ double g_sum1[HID], g_sq1[HID];
static __device__ double g_sum2[OUT_DIM], g_sq2[OUT_DIM];
static __device__ float  g_scale1[HID], g_shift1[HID];
static __device__ float  g_scale2[OUT_DIM], g_shift2[OUT_DIM];
// pre-split bf16 weight tiles: per buffer [hi 128x136][lo 128x136] halves
// g_w1t: 2 n-blocks; g_w2t: 2 k-chunks. 69632 B per buffer.
static __device__ __align__(16) unsigned char g_w1t[2 * 69632];
static __device__ __align__(16) unsigned char g_w2t[2 * 69632];

// ---------------- helpers ----------------
__device__ __forceinline__ uint32_t smem_u32(const void* p) {
    uint32_t a;
    asm("{ .reg .u64 t; cvta.to.shared.u64 t, %1; cvt.u32.u64 %0, t; }" : "=r"(a) : "l"(p));
    return a;
}
__device__ __forceinline__ void ldsm_x4(uint32_t a[4], uint32_t addr) {
    asm volatile("ldmatrix.sync.aligned.m8n8.x4.shared.b16 {%0,%1,%2,%3}, [%4];"
                 : "=r"(a[0]), "=r"(a[1]), "=r"(a[2]), "=r"(a[3]) : "r"(addr));
}
__device__ __forceinline__ void ldsm_x2(uint32_t b[2], uint32_t addr) {
    asm volatile("ldmatrix.sync.aligned.m8n8.x2.shared.b16 {%0,%1}, [%2];"
                 : "=r"(b[0]), "=r"(b[1]) : "r"(addr));
}
__device__ __forceinline__ void mma_bf16(float c[4], const uint32_t a[4], const uint32_t b[2]) {
    asm volatile("mma.sync.aligned.m16n8k16.row.col.f32.bf16.bf16.f32 "
                 "{%0,%1,%2,%3}, {%4,%5,%6,%7}, {%8,%9}, {%0,%1,%2,%3};"
                 : "+f"(c[0]), "+f"(c[1]), "+f"(c[2]), "+f"(c[3])
                 : "r"(a[0]), "r"(a[1]), "r"(a[2]), "r"(a[3]), "r"(b[0]), "r"(b[1]));
}
// split fp32 pair -> packed bf16x2 hi and lo
__device__ __forceinline__ void split2(float a, float b, uint32_t& hp, uint32_t& lp) {
    __nv_bfloat16 ha = __float2bfloat16(a), hb = __float2bfloat16(b);
    __nv_bfloat16 la = __float2bfloat16(a - __bfloat162float(ha));
    __nv_bfloat16 lb = __float2bfloat16(b - __bfloat162float(hb));
    hp = (uint32_t)__bfloat16_as_ushort(ha) | ((uint32_t)__bfloat16_as_ushort(hb) << 16);
    lp = (uint32_t)__bfloat16_as_ushort(la) | ((uint32_t)__bfloat16_as_ushort(lb) << 16);
}

// ---------------- init: aggr = (1+eps)*x ; zero stat accumulators ----------------
__global__ void init_kernel(const float4* __restrict__ x4, const float* __restrict__ eps) {
    int i = blockIdx.x * 256 + threadIdx.x;           // 3.2M float4 exactly
    float s = 1.0f + eps[0];
    float4 v = x4[i];
    v.x *= s; v.y *= s; v.z *= s; v.w *= s;
    ((float4*)g_aggr)[i] = v;
    if (blockIdx.x == 0) {
        int t = threadIdx.x;
        g_sum1[t] = 0.0; g_sq1[t] = 0.0;
        if (t < OUT_DIM) { g_sum2[t] = 0.0; g_sq2[t] = 0.0; }
    }
}

// ---------------- weight prep: fp32 -> bf16 hi/lo B^T tiles, stride 136 ----------------
// g_w1t buf nb: Bst[n][k] = W1[k][nb*128+n]   (n,k in [0,128))
// g_w2t buf c : Bst[n][k] = W2[c*128+k][n]
__global__ void prep_w_kernel(const float* __restrict__ W1, const float* __restrict__ W2) {
    int i = blockIdx.x * 256 + threadIdx.x;   // 65536 total
    if (i < 32768) {
        int nb = i >> 14, n = (i >> 7) & 127, k = i & 127;
        float v = W1[k * HID + nb * 128 + n];
        __nv_bfloat16 h = __float2bfloat16(v);
        __nv_bfloat16 l = __float2bfloat16(v - __bfloat162float(h));
        uint32_t off = (uint32_t)(n * 136 + k) * 2;
        *(__nv_bfloat16*)(g_w1t + nb * 69632 + off) = h;
        *(__nv_bfloat16*)(g_w1t + nb * 69632 + 34816 + off) = l;
    } else {
        int j = i - 32768;
        int c = j >> 14, n = (j >> 7) & 127, k = j & 127;
        float v = W2[(c * 128 + k) * OUT_DIM + n];
        __nv_bfloat16 h = __float2bfloat16(v);
        __nv_bfloat16 l = __float2bfloat16(v - __bfloat162float(h));
        uint32_t off = (uint32_t)(n * 136 + k) * 2;
        *(__nv_bfloat16*)(g_w2t + c * 69632 + off) = h;
        *(__nv_bfloat16*)(g_w2t + c * 69632 + 34816 + off) = l;
    }
}

// ---------------- scatter: aggr[dst] += x[src], one warp per edge ----------------
__global__ void scatter_kernel(const float4* __restrict__ x4, const int* __restrict__ ei) {
    int w    = (blockIdx.x * 256 + threadIdx.x) >> 5;
    int lane = threadIdx.x & 31;
    int s = __ldg(ei + w);
    int d = __ldg(ei + N_EDGES + w);
    float4 v = __ldg(x4 + (size_t)s * 32 + lane);
    float* p = g_aggr + (size_t)d * IN_DIM + lane * 4;
    asm volatile("red.global.add.v4.f32 [%0], {%1,%2,%3,%4};"
                 :: "l"(p), "f"(v.x), "f"(v.y), "f"(v.z), "f"(v.w) : "memory");
}

// ---------------- split-bf16 mma.sync GEMM, 128x128 CTA tile ----------------
// SMEM halves layout (byte offsets):
//   Ahi @ 0       (34816)    Alo @ 34816
//   B   @ 69632   (hi 34816 | lo 34816)
//   bias @ 139264 (512)  s_sum @ 139776 (512)  s_sq @ 140288 (512)
static constexpr int SOFF_ALO = 34816;
static constexpr int SOFF_B   = 69632;
static constexpr int SOFF_BI  = 139264;
static constexpr int SOFF_SS  = 139776;
static constexpr int SOFF_SQ  = 140288;
static constexpr int SMEM_GEMM = 140800;

template<int LDA, int NTOT, int KCHUNKS, bool FUSE_BN>
__device__ __forceinline__ void gemm_mma(const float* __restrict__ A,
                                         const unsigned char* __restrict__ Wt,
                                         const float* __restrict__ bias,
                                         float* __restrict__ out,
                                         double* __restrict__ stS, double* __restrict__ stQ,
                                         int M)
{
    extern __shared__ unsigned char smem[];
    const uint32_t sb = smem_u32(smem);
    const int tid = threadIdx.x;
    const int lane = tid & 31, wid = tid >> 5;
    const int warpM = wid & 3, warpN = wid >> 2;
    const int m0 = blockIdx.x * 128;
    const int n0g = blockIdx.y * 128;

    float* sbias = (float*)(smem + SOFF_BI);
    float* s_sum = (float*)(smem + SOFF_SS);
    float* s_sq  = (float*)(smem + SOFF_SQ);
    if (tid < 128) { sbias[tid] = bias[n0g + tid]; s_sum[tid] = 0.f; s_sq[tid] = 0.f; }

    float acc[2][8][4];
    #pragma unroll
    for (int mt = 0; mt < 2; mt++)
        #pragma unroll
        for (int nt = 0; nt < 8; nt++)
            #pragma unroll
            for (int r = 0; r < 4; r++) acc[mt][nt][r] = 0.f;

    // per-lane ldmatrix base offsets (bytes); row stride = 136 halves = 272 B
    const uint32_t a_off = (uint32_t)((warpM * 32 + (lane & 15)) * 136 + (lane >> 4) * 8) * 2;
    const uint32_t b_off = (uint32_t)((warpN * 64 + (lane & 7)) * 136 + ((lane >> 3) & 1) * 8) * 2;

    for (int kc = 0; kc < KCHUNKS; kc++) {
        // ---- load + (BN+ReLU) + split A chunk [128 x 128] -> Ahi/Alo smem ----
        #pragma unroll
        for (int i = 0; i < 16; i++) {
            int idx = tid + 256 * i;
            int row = idx >> 5;
            int c4  = (idx & 31) << 2;
            int gm  = m0 + row;
            float4 v = make_float4(0.f, 0.f, 0.f, 0.f);
            if (gm < M) {
                v = *(const float4*)(A + (size_t)gm * LDA + kc * 128 + c4);
                if (FUSE_BN) {
                    float4 sc = *(const float4*)(g_scale1 + kc * 128 + c4);
                    float4 sh = *(const float4*)(g_shift1 + kc * 128 + c4);
                    v.x = fmaxf(fmaf(v.x, sc.x, sh.x), 0.f);
                    v.y = fmaxf(fmaf(v.y, sc.y, sh.y), 0.f);
                    v.z = fmaxf(fmaf(v.z, sc.z, sh.z), 0.f);
                    v.w = fmaxf(fmaf(v.w, sc.w, sh.w), 0.f);
                }
            }
            uint32_t hp0, lp0, hp1, lp1;
            split2(v.x, v.y, hp0, lp0);
            split2(v.z, v.w, hp1, lp1);
            uint32_t o0 = (uint32_t)(row * 136 + c4) * 2;
            *(uint32_t*)(smem + o0)            = hp0;
            *(uint32_t*)(smem + o0 + 4)        = hp1;
            *(uint32_t*)(smem + SOFF_ALO + o0)     = lp0;
            *(uint32_t*)(smem + SOFF_ALO + o0 + 4) = lp1;
        }
        // ---- copy B chunk (hi+lo = 69632 B) ----
        {
            int buf = (KCHUNKS > 1) ? kc : (int)blockIdx.y;
            const float4* src = (const float4*)(Wt + buf * 69632);
            float4* dst = (float4*)(smem + SOFF_B);
            #pragma unroll
            for (int i = 0; i < 17; i++) dst[tid + 256 * i] = src[tid + 256 * i];
        }
        __syncthreads();

        // ---- mainloop: 8 k-steps of 16 ----
        const uint32_t sAhi = sb + a_off;
        const uint32_t sAlo = sb + SOFF_ALO + a_off;
        const uint32_t sBhi = sb + SOFF_B + b_off;
        const uint32_t sBlo = sb + SOFF_B + 34816 + b_off;
        #pragma unroll 2
        for (int ks = 0; ks < 8; ks++) {
            uint32_t ah[2][4], al[2][4];
            #pragma unroll
            for (int mt = 0; mt < 2; mt++) {
                ldsm_x4(ah[mt], sAhi + mt * 4352 + ks * 32);
                ldsm_x4(al[mt], sAlo + mt * 4352 + ks * 32);
            }
            #pragma unroll
            for (int nt = 0; nt < 8; nt++) {
                uint32_t bh[2], bl[2];
                ldsm_x2(bh, sBhi + nt * 2176 + ks * 32);
                ldsm_x2(bl, sBlo + nt * 2176 + ks * 32);
                #pragma unroll
                for (int mt = 0; mt < 2; mt++) {
                    mma_bf16(acc[mt][nt], ah[mt], bh);   // hi*hi
                    mma_bf16(acc[mt][nt], ah[mt], bl);   // hi*lo
                    mma_bf16(acc[mt][nt], al[mt], bh);   // lo*hi
                }
            }
        }
        __syncthreads();
    }

    // ---- epilogue: +bias, float2 stores, fused column stats ----
    const int mbase = m0 + warpM * 32 + (lane >> 2);
    #pragma unroll
    for (int nt = 0; nt < 8; nt++) {
        int cl = warpN * 64 + nt * 8 + 2 * (lane & 3);
        float b0 = sbias[cl], b1 = sbias[cl + 1];
        float cs0 = 0.f, cq0 = 0.f, cs1 = 0.f, cq1 = 0.f;
        #pragma unroll
        for (int mt = 0; mt < 2; mt++) {
            int mr = mbase + mt * 16;
            float v0 = acc[mt][nt][0] + b0, v1 = acc[mt][nt][1] + b1;
            if (mr < M) {
                *(float2*)(out + (size_t)mr * NTOT + n0g + cl) = make_float2(v0, v1);
                cs0 += v0; cq0 = fmaf(v0, v0, cq0);
                cs1 += v1; cq1 = fmaf(v1, v1, cq1);
            }
            float v2 = acc[mt][nt][2] + b0, v3 = acc[mt][nt][3] + b1;
            if (mr + 8 < M) {
                *(float2*)(out + (size_t)(mr + 8) * NTOT + n0g + cl) = make_float2(v2, v3);
                cs0 += v2; cq0 = fmaf(v2, v2, cq0);
                cs1 += v3; cq1 = fmaf(v3, v3, cq1);
            }
        }
        atomicAdd(&s_sum[cl], cs0);     atomicAdd(&s_sq[cl], cq0);
        atomicAdd(&s_sum[cl + 1], cs1); atomicAdd(&s_sq[cl + 1], cq1);
    }
    __syncthreads();
    if (tid < 128) {
        atomicAdd(&stS[n0g + tid], (double)s_sum[tid]);
        atomicAdd(&stQ[n0g + tid], (double)s_sq[tid]);
    }
}

__global__ void __launch_bounds__(256, 1)
gemm1_kernel(const float* __restrict__ b1) {
    gemm_mma<IN_DIM, HID, 1, false>(g_aggr, g_w1t, b1, g_h1, g_sum1, g_sq1, N_NODES);
}
__global__ void __launch_bounds__(256, 1)
gemm2_kernel(const float* __restrict__ b2, float* __restrict__ out) {
    gemm_mma<HID, OUT_DIM, 2, true>(g_h1, g_w2t, b2, out, g_sum2, g_sq2, N_NODES);
}

// ---------------- BN stats -> scale/shift ----------------
__global__ void stats1f_kernel(const float* __restrict__ g, const float* __restrict__ b) {
    int c = threadIdx.x;  // 256
    double invN = 1.0 / (double)N_NODES;
    double mu  = g_sum1[c] * invN;
    double var = g_sq1[c] * invN - mu * mu;
    float rstd = rsqrtf((float)var + 1e-5f);
    float sc = g[c] * rstd;
    g_scale1[c] = sc;
    g_shift1[c] = b[c] - (float)mu * sc;
}
__global__ void stats2f_kernel(const float* __restrict__ g, const float* __restrict__ b) {
    int c = threadIdx.x;  // 128
    double invN = 1.0 / (double)N_NODES;
    double mu  = g_sum2[c] * invN;
    double var = g_sq2[c] * invN - mu * mu;
    float rstd = rsqrtf((float)var + 1e-5f);
    float sc = g[c] * rstd;
    g_scale2[c] = sc;
    g_shift2[c] = b[c] - (float)mu * sc;
}

// ---------------- final: out = relu(out*scale2 + shift2) in place ----------------
__global__ void final_kernel(float4* __restrict__ out4) {
    int i = blockIdx.x * 256 + threadIdx.x;   // 3.2M float4 exactly
    float4 v = out4[i];
    int c4 = i & 31;
    float4 sc = ((const float4*)g_scale2)[c4];
    float4 sh = ((const float4*)g_shift2)[c4];
    v.x = fmaxf(fmaf(v.x, sc.x, sh.x), 0.f);
    v.y = fmaxf(fmaf(v.y, sc.y, sh.y), 0.f);
    v.z = fmaxf(fmaf(v.z, sc.z, sh.z), 0.f);
    v.w = fmaxf(fmaf(v.w, sc.w, sh.w), 0.f);
    out4[i] = v;
}

// ---------------- launch ----------------
extern "C" void kernel_launch(void* const* d_in, const int* in_sizes, int n_in,
                              void* d_out, int out_size) {
    const float* x     = (const float*)d_in[0];
    const int*   ei    = (const int*)  d_in[1];
    const float* eps   = (const float*)d_in[2];
    const float* W1    = (const float*)d_in[3];
    const float* b1    = (const float*)d_in[4];
    const float* g1    = (const float*)d_in[5];
    const float* beta1 = (const float*)d_in[6];
    const float* W2    = (const float*)d_in[7];
    const float* b2    = (const float*)d_in[8];
    const float* g2    = (const float*)d_in[9];
    const float* beta2 = (const float*)d_in[10];
    float* out = (float*)d_out;

    cudaFuncSetAttribute(gemm1_kernel, cudaFuncAttributeMaxDynamicSharedMemorySize, SMEM_GEMM);
    cudaFuncSetAttribute(gemm2_kernel, cudaFuncAttributeMaxDynamicSharedMemorySize, SMEM_GEMM);

    init_kernel<<<12500, 256>>>((const float4*)x, eps);
    prep_w_kernel<<<256, 256>>>(W1, W2);
    scatter_kernel<<<200000, 256>>>((const float4*)x, ei);

    dim3 g1d(782, 2);   // 128-row tiles x 2 n-blocks (HID=256)
    gemm1_kernel<<<g1d, 256, SMEM_GEMM>>>(b1);
    stats1f_kernel<<<1, HID>>>(g1, beta1);

    dim3 g2d(782, 1);   // OUT_DIM=128
    gemm2_kernel<<<g2d, 256, SMEM_GEMM>>>(b2, out);
    stats2f_kernel<<<1, OUT_DIM>>>(g2, beta2);

    final_kernel<<<12500, 256>>>((float4*)out);
}

// round 9
// speedup vs baseline: 1.2862x; 1.2862x over previous
#include <cuda_runtime.h>
#include <cuda_bf16.h>
#include <cstdint>

#define N_NODES 100000
#define N_EDGES 1600000
#define IN_DIM  128
#define HID     256
#define OUT_DIM 128

// ---------------- scratch (no allocations allowed) ----------------
static __device__ float  g_aggr[(size_t)N_NODES * IN_DIM];   // 51.2 MB
static __device__ float  g_h1[(size_t)N_NODES * HID];        // 102.4 MB
static __device__ double g_sum1[HID], g_sq1[HID];
static __device__ double g_sum2[OUT_DIM], g_sq2[OUT_DIM];
static __device__ float  g_scale1[HID], g_shift1[HID];
static __device__ float  g_scale2[OUT_DIM], g_shift2[OUT_DIM];
// pre-split bf16 weight tiles: per buffer [hi 128x136][lo 128x136] halves
// g_w1t: 2 n-blocks; g_w2t: 2 k-chunks. 69632 B per buffer.
static __device__ __align__(16) unsigned char g_w1t[2 * 69632];
static __device__ __align__(16) unsigned char g_w2t[2 * 69632];

// ---------------- helpers ----------------
__device__ __forceinline__ uint32_t smem_u32(const void* p) {
    uint32_t a;
    asm("{ .reg .u64 t; cvta.to.shared.u64 t, %1; cvt.u32.u64 %0, t; }" : "=r"(a) : "l"(p));
    return a;
}
__device__ __forceinline__ void ldsm_x4(uint32_t a[4], uint32_t addr) {
    asm volatile("ldmatrix.sync.aligned.m8n8.x4.shared.b16 {%0,%1,%2,%3}, [%4];"
                 : "=r"(a[0]), "=r"(a[1]), "=r"(a[2]), "=r"(a[3]) : "r"(addr));
}
__device__ __forceinline__ void mma_bf16(float c[4], const uint32_t a[4], const uint32_t b[2]) {
    asm volatile("mma.sync.aligned.m16n8k16.row.col.f32.bf16.bf16.f32 "
                 "{%0,%1,%2,%3}, {%4,%5,%6,%7}, {%8,%9}, {%0,%1,%2,%3};"
                 : "+f"(c[0]), "+f"(c[1]), "+f"(c[2]), "+f"(c[3])
                 : "r"(a[0]), "r"(a[1]), "r"(a[2]), "r"(a[3]), "r"(b[0]), "r"(b[1]));
}
// split fp32 pair -> packed bf16x2 hi and lo
__device__ __forceinline__ void split2(float a, float b, uint32_t& hp, uint32_t& lp) {
    __nv_bfloat16 ha = __float2bfloat16(a), hb = __float2bfloat16(b);
    __nv_bfloat16 la = __float2bfloat16(a - __bfloat162float(ha));
    __nv_bfloat16 lb = __float2bfloat16(b - __bfloat162float(hb));
    hp = (uint32_t)__bfloat16_as_ushort(ha) | ((uint32_t)__bfloat16_as_ushort(hb) << 16);
    lp = (uint32_t)__bfloat16_as_ushort(la) | ((uint32_t)__bfloat16_as_ushort(lb) << 16);
}

// ---------------- init: aggr = (1+eps)*x ; zero stat accumulators ----------------
__global__ void init_kernel(const float4* __restrict__ x4, const float* __restrict__ eps) {
    int i = blockIdx.x * 256 + threadIdx.x;           // 3.2M float4 exactly
    float s = 1.0f + eps[0];
    float4 v = x4[i];
    v.x *= s; v.y *= s; v.z *= s; v.w *= s;
    ((float4*)g_aggr)[i] = v;
    if (blockIdx.x == 0) {
        int t = threadIdx.x;
        g_sum1[t] = 0.0; g_sq1[t] = 0.0;
        if (t < OUT_DIM) { g_sum2[t] = 0.0; g_sq2[t] = 0.0; }
    }
}

// ---------------- weight prep: fp32 -> bf16 hi/lo B^T tiles, stride 136 ----------------
// g_w1t buf nb: Bst[n][k] = W1[k][nb*128+n]   (n,k in [0,128))
// g_w2t buf c : Bst[n][k] = W2[c*128+k][n]
__global__ void prep_w_kernel(const float* __restrict__ W1, const float* __restrict__ W2) {
    int i = blockIdx.x * 256 + threadIdx.x;   // 65536 total
    if (i < 32768) {
        int nb = i >> 14, n = (i >> 7) & 127, k = i & 127;
        float v = W1[k * HID + nb * 128 + n];
        __nv_bfloat16 h = __float2bfloat16(v);
        __nv_bfloat16 l = __float2bfloat16(v - __bfloat162float(h));
        uint32_t off = (uint32_t)(n * 136 + k) * 2;
        *(__nv_bfloat16*)(g_w1t + nb * 69632 + off) = h;
        *(__nv_bfloat16*)(g_w1t + nb * 69632 + 34816 + off) = l;
    } else {
        int j = i - 32768;
        int c = j >> 14, n = (j >> 7) & 127, k = j & 127;
        float v = W2[(c * 128 + k) * OUT_DIM + n];
        __nv_bfloat16 h = __float2bfloat16(v);
        __nv_bfloat16 l = __float2bfloat16(v - __bfloat162float(h));
        uint32_t off = (uint32_t)(n * 136 + k) * 2;
        *(__nv_bfloat16*)(g_w2t + c * 69632 + off) = h;
        *(__nv_bfloat16*)(g_w2t + c * 69632 + 34816 + off) = l;
    }
}

// ---------------- scatter: aggr[dst] += x[src], one warp per edge ----------------
__global__ void scatter_kernel(const float4* __restrict__ x4, const int* __restrict__ ei) {
    int w    = (blockIdx.x * 256 + threadIdx.x) >> 5;
    int lane = threadIdx.x & 31;
    int s = __ldg(ei + w);
    int d = __ldg(ei + N_EDGES + w);
    float4 v = __ldg(x4 + (size_t)s * 32 + lane);
    float* p = g_aggr + (size_t)d * IN_DIM + lane * 4;
    asm volatile("red.global.add.v4.f32 [%0], {%1,%2,%3,%4};"
                 :: "l"(p), "f"(v.x), "f"(v.y), "f"(v.z), "f"(v.w) : "memory");
}

// ---------------- split-bf16 mma.sync GEMM, 64x128 CTA tile, 2 CTAs/SM ----------------
// SMEM layout (byte offsets):
//   Ahi @ 0      (17408 = 64*272)    Alo @ 17408
//   B   @ 34816  (hi 34816 | lo 34816)
//   bias @ 104448 (512)  s_sum @ 104960 (512)  s_sq @ 105472 (512)
static constexpr int SOFF_ALO = 17408;
static constexpr int SOFF_B   = 34816;
static constexpr int SOFF_BI  = 104448;
static constexpr int SOFF_SS  = 104960;
static constexpr int SOFF_SQ  = 105472;
static constexpr int SMEM_GEMM = 105984;

template<int LDA, int NTOT, int KCHUNKS, bool FUSE_BN>
__device__ __forceinline__ void gemm_mma(const float* __restrict__ A,
                                         const unsigned char* __restrict__ Wt,
                                         const float* __restrict__ bias,
                                         float* __restrict__ out,
                                         double* __restrict__ stS, double* __restrict__ stQ,
                                         int M)
{
    extern __shared__ unsigned char smem[];
    const uint32_t sb = smem_u32(smem);
    const int tid = threadIdx.x;
    const int lane = tid & 31, wid = tid >> 5;
    const int warpM = wid & 1, warpN = wid >> 1;     // 2 x 4 warp grid, warp tile 32x32
    const int m0 = blockIdx.x * 64;
    const int n0g = blockIdx.y * 128;

    float* sbias = (float*)(smem + SOFF_BI);
    float* s_sum = (float*)(smem + SOFF_SS);
    float* s_sq  = (float*)(smem + SOFF_SQ);
    if (tid < 128) { sbias[tid] = bias[n0g + tid]; s_sum[tid] = 0.f; s_sq[tid] = 0.f; }

    float acc[2][4][4];
    #pragma unroll
    for (int mt = 0; mt < 2; mt++)
        #pragma unroll
        for (int nt = 0; nt < 4; nt++)
            #pragma unroll
            for (int r = 0; r < 4; r++) acc[mt][nt][r] = 0.f;

    // per-lane ldmatrix base offsets (bytes); row stride = 136 halves = 272 B
    const uint32_t a_off = (uint32_t)(warpM * 32 + (lane & 15)) * 272 + (uint32_t)(lane >> 4) * 16;
    // B x4: lanes 0-7 -> nt_even k0-7, 8-15 -> nt_even k8-15, 16-23 -> nt_odd k0-7, 24-31 -> nt_odd k8-15
    const uint32_t b_off = (uint32_t)(warpN * 32 + ((lane >> 4) & 1) * 8 + (lane & 7)) * 272
                         + (uint32_t)((lane >> 3) & 1) * 16;

    for (int kc = 0; kc < KCHUNKS; kc++) {
        // ---- load + (BN+ReLU) + split A chunk [64 x 128] -> Ahi/Alo smem ----
        #pragma unroll
        for (int i = 0; i < 8; i++) {
            int idx = tid + 256 * i;              // 2048 float4
            int row = idx >> 5;
            int c4  = (idx & 31) << 2;
            int gm  = m0 + row;
            float4 v = make_float4(0.f, 0.f, 0.f, 0.f);
            if (gm < M) {
                v = *(const float4*)(A + (size_t)gm * LDA + kc * 128 + c4);
                if (FUSE_BN) {
                    float4 sc = *(const float4*)(g_scale1 + kc * 128 + c4);
                    float4 sh = *(const float4*)(g_shift1 + kc * 128 + c4);
                    v.x = fmaxf(fmaf(v.x, sc.x, sh.x), 0.f);
                    v.y = fmaxf(fmaf(v.y, sc.y, sh.y), 0.f);
                    v.z = fmaxf(fmaf(v.z, sc.z, sh.z), 0.f);
                    v.w = fmaxf(fmaf(v.w, sc.w, sh.w), 0.f);
                }
            }
            uint32_t hp0, lp0, hp1, lp1;
            split2(v.x, v.y, hp0, lp0);
            split2(v.z, v.w, hp1, lp1);
            uint32_t o0 = (uint32_t)(row * 136 + c4) * 2;
            *(uint32_t*)(smem + o0)                = hp0;
            *(uint32_t*)(smem + o0 + 4)            = hp1;
            *(uint32_t*)(smem + SOFF_ALO + o0)     = lp0;
            *(uint32_t*)(smem + SOFF_ALO + o0 + 4) = lp1;
        }
        // ---- copy B chunk (hi+lo = 69632 B) ----
        {
            int buf = (KCHUNKS > 1) ? kc : (int)blockIdx.y;
            const float4* src = (const float4*)(Wt + buf * 69632);
            float4* dst = (float4*)(smem + SOFF_B);
            #pragma unroll
            for (int i = 0; i < 17; i++) dst[tid + 256 * i] = src[tid + 256 * i];
        }
        __syncthreads();

        // ---- mainloop: 8 k-steps of 16, term-major for independent MMA chains ----
        const uint32_t sAhi = sb + a_off;
        const uint32_t sAlo = sb + SOFF_ALO + a_off;
        const uint32_t sBhi = sb + SOFF_B + b_off;
        const uint32_t sBlo = sb + SOFF_B + 34816 + b_off;
        #pragma unroll
        for (int ks = 0; ks < 8; ks++) {
            uint32_t ah[2][4], al[2][4];
            ldsm_x4(ah[0], sAhi + ks * 32);
            ldsm_x4(ah[1], sAhi + 4352 + ks * 32);      // +16 rows
            ldsm_x4(al[0], sAlo + ks * 32);
            ldsm_x4(al[1], sAlo + 4352 + ks * 32);
            uint32_t bh[4][2], bl[4][2];
            #pragma unroll
            for (int np = 0; np < 2; np++) {
                uint32_t t[4];
                ldsm_x4(t, sBhi + np * 4352 + ks * 32); // 2 n-tiles per ldsm
                bh[2*np][0] = t[0]; bh[2*np][1] = t[1];
                bh[2*np+1][0] = t[2]; bh[2*np+1][1] = t[3];
                ldsm_x4(t, sBlo + np * 4352 + ks * 32);
                bl[2*np][0] = t[0]; bl[2*np][1] = t[1];
                bl[2*np+1][0] = t[2]; bl[2*np+1][1] = t[3];
            }
            // pass 1: hi*hi — 8 independent accumulators
            #pragma unroll
            for (int mt = 0; mt < 2; mt++)
                #pragma unroll
                for (int nt = 0; nt < 4; nt++) mma_bf16(acc[mt][nt], ah[mt], bh[nt]);
            // pass 2: hi*lo
            #pragma unroll
            for (int mt = 0; mt < 2; mt++)
                #pragma unroll
                for (int nt = 0; nt < 4; nt++) mma_bf16(acc[mt][nt], ah[mt], bl[nt]);
            // pass 3: lo*hi
            #pragma unroll
            for (int mt = 0; mt < 2; mt++)
                #pragma unroll
                for (int nt = 0; nt < 4; nt++) mma_bf16(acc[mt][nt], al[mt], bh[nt]);
        }
        __syncthreads();
    }

    // ---- epilogue: +bias, float2 stores, fused column stats ----
    const int mbase = m0 + warpM * 32 + (lane >> 2);
    #pragma unroll
    for (int nt = 0; nt < 4; nt++) {
        int cl = warpN * 32 + nt * 8 + 2 * (lane & 3);
        float b0 = sbias[cl], b1 = sbias[cl + 1];
        float cs0 = 0.f, cq0 = 0.f, cs1 = 0.f, cq1 = 0.f;
        #pragma unroll
        for (int mt = 0; mt < 2; mt++) {
            int mr = mbase + mt * 16;
            float v0 = acc[mt][nt][0] + b0, v1 = acc[mt][nt][1] + b1;
            if (mr < M) {
                *(float2*)(out + (size_t)mr * NTOT + n0g + cl) = make_float2(v0, v1);
                cs0 += v0; cq0 = fmaf(v0, v0, cq0);
                cs1 += v1; cq1 = fmaf(v1, v1, cq1);
            }
            float v2 = acc[mt][nt][2] + b0, v3 = acc[mt][nt][3] + b1;
            if (mr + 8 < M) {
                *(float2*)(out + (size_t)(mr + 8) * NTOT + n0g + cl) = make_float2(v2, v3);
                cs0 += v2; cq0 = fmaf(v2, v2, cq0);
                cs1 += v3; cq1 = fmaf(v3, v3, cq1);
            }
        }
        atomicAdd(&s_sum[cl], cs0);     atomicAdd(&s_sq[cl], cq0);
        atomicAdd(&s_sum[cl + 1], cs1); atomicAdd(&s_sq[cl + 1], cq1);
    }
    __syncthreads();
    if (tid < 128) {
        atomicAdd(&stS[n0g + tid], (double)s_sum[tid]);
        atomicAdd(&stQ[n0g + tid], (double)s_sq[tid]);
    }
}

__global__ void __launch_bounds__(256, 2)
gemm1_kernel(const float* __restrict__ b1) {
    gemm_mma<IN_DIM, HID, 1, false>(g_aggr, g_w1t, b1, g_h1, g_sum1, g_sq1, N_NODES);
}
__global__ void __launch_bounds__(256, 2)
gemm2_kernel(const float* __restrict__ b2, float* __restrict__ out) {
    gemm_mma<HID, OUT_DIM, 2, true>(g_h1, g_w2t, b2, out, g_sum2, g_sq2, N_NODES);
}

// ---------------- BN stats -> scale/shift ----------------
__global__ void stats1f_kernel(const float* __restrict__ g, const float* __restrict__ b) {
    int c = threadIdx.x;  // 256
    double invN = 1.0 / (double)N_NODES;
    double mu  = g_sum1[c] * invN;
    double var = g_sq1[c] * invN - mu * mu;
    float rstd = rsqrtf((float)var + 1e-5f);
    float sc = g[c] * rstd;
    g_scale1[c] = sc;
    g_shift1[c] = b[c] - (float)mu * sc;
}
__global__ void stats2f_kernel(const float* __restrict__ g, const float* __restrict__ b) {
    int c = threadIdx.x;  // 128
    double invN = 1.0 / (double)N_NODES;
    double mu  = g_sum2[c] * invN;
    double var = g_sq2[c] * invN - mu * mu;
    float rstd = rsqrtf((float)var + 1e-5f);
    float sc = g[c] * rstd;
    g_scale2[c] = sc;
    g_shift2[c] = b[c] - (float)mu * sc;
}

// ---------------- final: out = relu(out*scale2 + shift2) in place ----------------
__global__ void final_kernel(float4* __restrict__ out4) {
    int i = blockIdx.x * 256 + threadIdx.x;   // 3.2M float4 exactly
    float4 v = out4[i];
    int c4 = i & 31;
    float4 sc = ((const float4*)g_scale2)[c4];
    float4 sh = ((const float4*)g_shift2)[c4];
    v.x = fmaxf(fmaf(v.x, sc.x, sh.x), 0.f);
    v.y = fmaxf(fmaf(v.y, sc.y, sh.y), 0.f);
    v.z = fmaxf(fmaf(v.z, sc.z, sh.z), 0.f);
    v.w = fmaxf(fmaf(v.w, sc.w, sh.w), 0.f);
    out4[i] = v;
}

// ---------------- launch ----------------
extern "C" void kernel_launch(void* const* d_in, const int* in_sizes, int n_in,
                              void* d_out, int out_size) {
    const float* x     = (const float*)d_in[0];
    const int*   ei    = (const int*)  d_in[1];
    const float* eps   = (const float*)d_in[2];
    const float* W1    = (const float*)d_in[3];
    const float* b1    = (const float*)d_in[4];
    const float* g1    = (const float*)d_in[5];
    const float* beta1 = (const float*)d_in[6];
    const float* W2    = (const float*)d_in[7];
    const float* b2    = (const float*)d_in[8];
    const float* g2    = (const float*)d_in[9];
    const float* beta2 = (const float*)d_in[10];
    float* out = (float*)d_out;

    cudaFuncSetAttribute(gemm1_kernel, cudaFuncAttributeMaxDynamicSharedMemorySize, SMEM_GEMM);
    cudaFuncSetAttribute(gemm2_kernel, cudaFuncAttributeMaxDynamicSharedMemorySize, SMEM_GEMM);

    init_kernel<<<12500, 256>>>((const float4*)x, eps);
    prep_w_kernel<<<256, 256>>>(W1, W2);
    scatter_kernel<<<200000, 256>>>((const float4*)x, ei);

    dim3 g1d((N_NODES + 63) / 64, 2);   // 1563 x 2 (HID=256 in two 128-col blocks)
    gemm1_kernel<<<g1d, 256, SMEM_GEMM>>>(b1);
    stats1f_kernel<<<1, HID>>>(g1, beta1);

    dim3 g2d((N_NODES + 63) / 64, 1);   // OUT_DIM=128
    gemm2_kernel<<<g2d, 256, SMEM_GEMM>>>(b2, out);
    stats2f_kernel<<<1, OUT_DIM>>>(g2, beta2);

    final_kernel<<<12500, 256>>>((float4*)out);
}

// round 13
// speedup vs baseline: 1.5879x; 1.2346x over previous
#include <cuda_runtime.h>
#include <cuda_bf16.h>
#include <cstdint>

#define N_NODES 100000
#define N_EDGES 1600000
#define IN_DIM  128
#define HID     256
#define OUT_DIM 128

#define PAD_ROWS 100096
#define ROW_B    272                      // 136 halves, 16-half padded row
#define PLANE    ((size_t)PAD_ROWS * ROW_B)   // 27,226,112 B
#define NTILES_M 1563
#define GRID_X   148

// ---------------- scratch (no allocations allowed) ----------------
static __device__ float  g_aggr[(size_t)N_NODES * IN_DIM];   // 51.2 MB
static __device__ float  g_h1[(size_t)N_NODES * HID];        // 102.4 MB
static __device__ double g_sum1[HID], g_sq1[HID];
static __device__ double g_sum2[OUT_DIM], g_sq2[OUT_DIM];
static __device__ float  g_scale1[HID], g_shift1[HID];
static __device__ float  g_scale2[OUT_DIM], g_shift2[OUT_DIM];
// pre-split bf16 weight tiles: per buffer [hi 128x136][lo 128x136] halves
static __device__ __align__(16) unsigned char g_w1t[2 * 69632];
static __device__ __align__(16) unsigned char g_w2t[2 * 69632];
// pre-split bf16 activations, padded rows (tail rows stay zero-initialized)
static __device__ __align__(16) unsigned char g_ahi[27226112];
static __device__ __align__(16) unsigned char g_alo[27226112];
static __device__ __align__(16) unsigned char g_h1hi[2 * 27226112];  // [kc][row][136h]
static __device__ __align__(16) unsigned char g_h1lo[2 * 27226112];

// ---------------- helpers ----------------
__device__ __forceinline__ uint32_t smem_u32(const void* p) {
    uint32_t a;
    asm("{ .reg .u64 t; cvta.to.shared.u64 t, %1; cvt.u32.u64 %0, t; }" : "=r"(a) : "l"(p));
    return a;
}
__device__ __forceinline__ void ldsm_x4(uint32_t a[4], uint32_t addr) {
    asm volatile("ldmatrix.sync.aligned.m8n8.x4.shared.b16 {%0,%1,%2,%3}, [%4];"
                 : "=r"(a[0]), "=r"(a[1]), "=r"(a[2]), "=r"(a[3]) : "r"(addr));
}
__device__ __forceinline__ void mma_bf16(float c[4], const uint32_t a[4], const uint32_t b[2]) {
    asm volatile("mma.sync.aligned.m16n8k16.row.col.f32.bf16.bf16.f32 "
                 "{%0,%1,%2,%3}, {%4,%5,%6,%7}, {%8,%9}, {%0,%1,%2,%3};"
                 : "+f"(c[0]), "+f"(c[1]), "+f"(c[2]), "+f"(c[3])
                 : "r"(a[0]), "r"(a[1]), "r"(a[2]), "r"(a[3]), "r"(b[0]), "r"(b[1]));
}
__device__ __forceinline__ void cpa16(uint32_t dst, const void* src) {
    asm volatile("cp.async.cg.shared.global [%0], [%1], 16;" :: "r"(dst), "l"(src));
}
#define CP_COMMIT() asm volatile("cp.async.commit_group;" ::: "memory")
#define CP_WAIT0()  asm volatile("cp.async.wait_group 0;" ::: "memory")

// split fp32 pair -> packed bf16x2 hi and lo
__device__ __forceinline__ void split2(float a, float b, uint32_t& hp, uint32_t& lp) {
    __nv_bfloat16 ha = __float2bfloat16(a), hb = __float2bfloat16(b);
    __nv_bfloat16 la = __float2bfloat16(a - __bfloat162float(ha));
    __nv_bfloat16 lb = __float2bfloat16(b - __bfloat162float(hb));
    hp = (uint32_t)__bfloat16_as_ushort(ha) | ((uint32_t)__bfloat16_as_ushort(hb) << 16);
    lp = (uint32_t)__bfloat16_as_ushort(la) | ((uint32_t)__bfloat16_as_ushort(lb) << 16);
}

// ---------------- init: aggr = (1+eps)*x ; zero stat accumulators ----------------
__global__ void init_kernel(const float4* __restrict__ x4, const float* __restrict__ eps) {
    int i = blockIdx.x * 256 + threadIdx.x;           // 3.2M float4 exactly
    float s = 1.0f + eps[0];
    float4 v = x4[i];
    v.x *= s; v.y *= s; v.z *= s; v.w *= s;
    ((float4*)g_aggr)[i] = v;
    if (blockIdx.x == 0) {
        int t = threadIdx.x;
        g_sum1[t] = 0.0; g_sq1[t] = 0.0;
        if (t < OUT_DIM) { g_sum2[t] = 0.0; g_sq2[t] = 0.0; }
    }
}

// ---------------- weight prep: fp32 -> bf16 hi/lo B^T tiles, stride 136 ----------------
__global__ void prep_w_kernel(const float* __restrict__ W1, const float* __restrict__ W2) {
    int i = blockIdx.x * 256 + threadIdx.x;   // 65536 total
    if (i < 32768) {
        int nb = i >> 14, n = (i >> 7) & 127, k = i & 127;
        float v = W1[k * HID + nb * 128 + n];
        __nv_bfloat16 h = __float2bfloat16(v);
        __nv_bfloat16 l = __float2bfloat16(v - __bfloat162float(h));
        uint32_t off = (uint32_t)(n * 136 + k) * 2;
        *(__nv_bfloat16*)(g_w1t + nb * 69632 + off) = h;
        *(__nv_bfloat16*)(g_w1t + nb * 69632 + 34816 + off) = l;
    } else {
        int j = i - 32768;
        int c = j >> 14, n = (j >> 7) & 127, k = j & 127;
        float v = W2[(c * 128 + k) * OUT_DIM + n];
        __nv_bfloat16 h = __float2bfloat16(v);
        __nv_bfloat16 l = __float2bfloat16(v - __bfloat162float(h));
        uint32_t off = (uint32_t)(n * 136 + k) * 2;
        *(__nv_bfloat16*)(g_w2t + c * 69632 + off) = h;
        *(__nv_bfloat16*)(g_w2t + c * 69632 + 34816 + off) = l;
    }
}

// ---------------- scatter: aggr[dst] += x[src], one warp per edge ----------------
__global__ void scatter_kernel(const float4* __restrict__ x4, const int* __restrict__ ei) {
    int w    = (blockIdx.x * 256 + threadIdx.x) >> 5;
    int lane = threadIdx.x & 31;
    int s = __ldg(ei + w);
    int d = __ldg(ei + N_EDGES + w);
    float4 v = __ldg(x4 + (size_t)s * 32 + lane);
    float* p = g_aggr + (size_t)d * IN_DIM + lane * 4;
    asm volatile("red.global.add.v4.f32 [%0], {%1,%2,%3,%4};"
                 :: "l"(p), "f"(v.x), "f"(v.y), "f"(v.z), "f"(v.w) : "memory");
}

// ---------------- prepass 1: split aggr fp32 -> g_ahi/g_alo ----------------
__global__ void split_aggr_kernel() {
    int i = blockIdx.x * 256 + threadIdx.x;   // 3.2M
    int row = i >> 5, c4 = (i & 31) << 2;
    float4 v = *(const float4*)(g_aggr + (size_t)row * IN_DIM + c4);
    uint32_t hp0, lp0, hp1, lp1;
    split2(v.x, v.y, hp0, lp0);
    split2(v.z, v.w, hp1, lp1);
    size_t off = (size_t)row * ROW_B + c4 * 2;
    *(uint32_t*)(g_ahi + off)     = hp0;
    *(uint32_t*)(g_ahi + off + 4) = hp1;
    *(uint32_t*)(g_alo + off)     = lp0;
    *(uint32_t*)(g_alo + off + 4) = lp1;
}

// ---------------- prepass 2: h1 -> BN+ReLU -> split -> g_h1hi/lo (chunk-major) ----------------
__global__ void split_h1_kernel() {
    int i = blockIdx.x * 256 + threadIdx.x;   // 6.4M
    int row = i >> 6, c4 = (i & 63) << 2;
    float4 v  = *(const float4*)(g_h1 + (size_t)row * HID + c4);
    float4 sc = *(const float4*)(g_scale1 + c4);
    float4 sh = *(const float4*)(g_shift1 + c4);
    v.x = fmaxf(fmaf(v.x, sc.x, sh.x), 0.f);
    v.y = fmaxf(fmaf(v.y, sc.y, sh.y), 0.f);
    v.z = fmaxf(fmaf(v.z, sc.z, sh.z), 0.f);
    v.w = fmaxf(fmaf(v.w, sc.w, sh.w), 0.f);
    uint32_t hp0, lp0, hp1, lp1;
    split2(v.x, v.y, hp0, lp0);
    split2(v.z, v.w, hp1, lp1);
    int kc = c4 >> 7, kin = c4 & 127;
    size_t off = (size_t)kc * PLANE + (size_t)row * ROW_B + kin * 2;
    *(uint32_t*)(g_h1hi + off)     = hp0;
    *(uint32_t*)(g_h1hi + off + 4) = hp1;
    *(uint32_t*)(g_h1lo + off)     = lp0;
    *(uint32_t*)(g_h1lo + off + 4) = lp1;
}

// ---------------- persistent split-bf16 mma.sync GEMM ----------------
// SMEM: A @ 0 (hi 17408 | lo 17408), B @ 34816 (69632), bias @ 104448,
//       s_sum @ 104960, s_sq @ 105472. Total 105984 -> 2 CTAs/SM.
static constexpr int SOFF_B  = 34816;
static constexpr int SOFF_BI = 104448;
static constexpr int SOFF_SS = 104960;
static constexpr int SOFF_SQ = 105472;
static constexpr int SMEM_GEMM = 105984;

// NT = n-tiles per warp (4 -> NCOLS=128, 2 -> NCOLS=64). Warp grid 2(M) x 4(N).
template<int NT, int KCHUNKS, int NTOT>
__global__ void __launch_bounds__(256, 2)
gemm_k(const unsigned char* __restrict__ Ahi, const unsigned char* __restrict__ Alo,
       const unsigned char* __restrict__ Bsrc, const float* __restrict__ bias,
       float* __restrict__ out, double* __restrict__ stS, double* __restrict__ stQ)
{
    constexpr int NCOLS = NT * 32;
    constexpr int BHALF = (KCHUNKS == 1) ? 34816 : 17408;
    extern __shared__ unsigned char smem[];
    const uint32_t sb = smem_u32(smem);
    const int tid = threadIdx.x;
    const int lane = tid & 31, wid = tid >> 5;
    const int warpM = wid & 1, warpN = wid >> 1;
    const int y = blockIdx.y;
    const int n0g = y * NCOLS;

    float* sbias = (float*)(smem + SOFF_BI);
    float* s_sum = (float*)(smem + SOFF_SS);
    float* s_sq  = (float*)(smem + SOFF_SQ);
    if (tid < NCOLS) { sbias[tid] = bias[n0g + tid]; s_sum[tid] = 0.f; s_sq[tid] = 0.f; }

    // ---- load B once (69632 B) ----
    if (KCHUNKS == 1) {
        const unsigned char* bs = Bsrc + (size_t)y * 69632;
        for (int i = tid; i < 4352; i += 256) cpa16(sb + SOFF_B + i * 16, bs + (size_t)i * 16);
    } else {
        for (int i = tid; i < 4352; i += 256) {
            int piece = i / 1088, win = i % 1088;
            int kc = piece >> 1, hf = piece & 1;
            cpa16(sb + SOFF_B + kc * 34816 + hf * 17408 + win * 16,
                  Bsrc + (size_t)kc * 69632 + (size_t)hf * 34816 + (size_t)y * 17408 + (size_t)win * 16);
        }
    }
    CP_COMMIT(); CP_WAIT0();
    __syncthreads();

    // per-lane ldmatrix offsets (row stride 272 B)
    const uint32_t a_off = (uint32_t)(warpM * 32 + (lane & 15)) * 272 + (uint32_t)(lane >> 4) * 16;
    const uint32_t b_off = (uint32_t)(warpN * (NT * 8) + ((lane >> 4) & 1) * 8 + (lane & 7)) * 272
                         + (uint32_t)((lane >> 3) & 1) * 16;

    float st[NT][4];
    #pragma unroll
    for (int nt = 0; nt < NT; nt++)
        #pragma unroll
        for (int r = 0; r < 4; r++) st[nt][r] = 0.f;

    for (int t = blockIdx.x; t < NTILES_M; t += GRID_X) {
        float acc[2][NT][4];
        #pragma unroll
        for (int mt = 0; mt < 2; mt++)
            #pragma unroll
            for (int nt = 0; nt < NT; nt++)
                #pragma unroll
                for (int r = 0; r < 4; r++) acc[mt][nt][r] = 0.f;

        #pragma unroll
        for (int kc = 0; kc < KCHUNKS; kc++) {
            // ---- A copy: 34816 B pre-split, contiguous per half ----
            size_t abase = (size_t)t * 17408 + (size_t)kc * PLANE;
            #pragma unroll
            for (int ii = 0; ii < 9; ii++) {
                int i = tid + 256 * ii;
                if (i < 2176) {
                    const unsigned char* s = (i < 1088 ? Ahi : Alo) + abase + (size_t)(i % 1088) * 16;
                    cpa16(sb + i * 16, s);
                }
            }
            CP_COMMIT(); CP_WAIT0();
            __syncthreads();

            const uint32_t sAhi = sb + a_off;
            const uint32_t sAlo = sAhi + 17408;
            const uint32_t sBhi = sb + SOFF_B + (KCHUNKS == 2 ? kc * 34816 : 0) + b_off;
            #pragma unroll
            for (int ks = 0; ks < 8; ks++) {
                uint32_t ah[2][4], al[2][4];
                ldsm_x4(ah[0], sAhi + ks * 32);
                ldsm_x4(ah[1], sAhi + 4352 + ks * 32);
                ldsm_x4(al[0], sAlo + ks * 32);
                ldsm_x4(al[1], sAlo + 4352 + ks * 32);
                uint32_t bh[NT][2], bl[NT][2];
                #pragma unroll
                for (int np = 0; np < NT / 2; np++) {
                    uint32_t tt[4];
                    ldsm_x4(tt, sBhi + np * 4352 + ks * 32);
                    bh[2*np][0] = tt[0]; bh[2*np][1] = tt[1];
                    bh[2*np+1][0] = tt[2]; bh[2*np+1][1] = tt[3];
                    ldsm_x4(tt, sBhi + BHALF + np * 4352 + ks * 32);
                    bl[2*np][0] = tt[0]; bl[2*np][1] = tt[1];
                    bl[2*np+1][0] = tt[2]; bl[2*np+1][1] = tt[3];
                }
                #pragma unroll
                for (int mt = 0; mt < 2; mt++)
                    #pragma unroll
                    for (int nt = 0; nt < NT; nt++) mma_bf16(acc[mt][nt], ah[mt], bh[nt]);
                #pragma unroll
                for (int mt = 0; mt < 2; mt++)
                    #pragma unroll
                    for (int nt = 0; nt < NT; nt++) mma_bf16(acc[mt][nt], ah[mt], bl[nt]);
                #pragma unroll
                for (int mt = 0; mt < 2; mt++)
                    #pragma unroll
                    for (int nt = 0; nt < NT; nt++) mma_bf16(acc[mt][nt], al[mt], bh[nt]);
            }
            __syncthreads();   // A buffer reused next chunk/tile
        }

        // ---- epilogue: +bias, stores, register stats ----
        const int mbase = t * 64 + warpM * 32 + (lane >> 2);
        #pragma unroll
        for (int nt = 0; nt < NT; nt++) {
            int cl = warpN * (NT * 8) + nt * 8 + 2 * (lane & 3);
            float b0 = sbias[cl], b1 = sbias[cl + 1];
            #pragma unroll
            for (int mt = 0; mt < 2; mt++) {
                int mr = mbase + mt * 16;
                if (mr < N_NODES) {
                    float v0 = acc[mt][nt][0] + b0, v1 = acc[mt][nt][1] + b1;
                    *(float2*)(out + (size_t)mr * NTOT + n0g + cl) = make_float2(v0, v1);
                    st[nt][0] += v0; st[nt][1] = fmaf(v0, v0, st[nt][1]);
                    st[nt][2] += v1; st[nt][3] = fmaf(v1, v1, st[nt][3]);
                }
                if (mr + 8 < N_NODES) {
                    float v2 = acc[mt][nt][2] + b0, v3 = acc[mt][nt][3] + b1;
                    *(float2*)(out + (size_t)(mr + 8) * NTOT + n0g + cl) = make_float2(v2, v3);
                    st[nt][0] += v2; st[nt][1] = fmaf(v2, v2, st[nt][1]);
                    st[nt][2] += v3; st[nt][3] = fmaf(v3, v3, st[nt][3]);
                }
            }
        }
    }

    // ---- flush stats once ----
    __syncthreads();
    #pragma unroll
    for (int nt = 0; nt < NT; nt++) {
        int cl = warpN * (NT * 8) + nt * 8 + 2 * (lane & 3);
        atomicAdd(&s_sum[cl],     st[nt][0]);
        atomicAdd(&s_sq[cl],      st[nt][1]);
        atomicAdd(&s_sum[cl + 1], st[nt][2]);
        atomicAdd(&s_sq[cl + 1],  st[nt][3]);
    }
    __syncthreads();
    if (tid < NCOLS) {
        atomicAdd(&stS[n0g + tid], (double)s_sum[tid]);
        atomicAdd(&stQ[n0g + tid], (double)s_sq[tid]);
    }
}

// ---------------- BN stats -> scale/shift ----------------
__global__ void stats1f_kernel(const float* __restrict__ g, const float* __restrict__ b) {
    int c = threadIdx.x;  // 256
    double invN = 1.0 / (double)N_NODES;
    double mu  = g_sum1[c] * invN;
    double var = g_sq1[c] * invN - mu * mu;
    float rstd = rsqrtf((float)var + 1e-5f);
    float sc = g[c] * rstd;
    g_scale1[c] = sc;
    g_shift1[c] = b[c] - (float)mu * sc;
}
__global__ void stats2f_kernel(const float* __restrict__ g, const float* __restrict__ b) {
    int c = threadIdx.x;  // 128
    double invN = 1.0 / (double)N_NODES;
    double mu  = g_sum2[c] * invN;
    double var = g_sq2[c] * invN - mu * mu;
    float rstd = rsqrtf((float)var + 1e-5f);
    float sc = g[c] * rstd;
    g_scale2[c] = sc;
    g_shift2[c] = b[c] - (float)mu * sc;
}

// ---------------- final: out = relu(out*scale2 + shift2) in place ----------------
__global__ void final_kernel(float4* __restrict__ out4) {
    int i = blockIdx.x * 256 + threadIdx.x;   // 3.2M float4 exactly
    float4 v = out4[i];
    int c4 = i & 31;
    float4 sc = ((const float4*)g_scale2)[c4];
    float4 sh = ((const float4*)g_shift2)[c4];
    v.x = fmaxf(fmaf(v.x, sc.x, sh.x), 0.f);
    v.y = fmaxf(fmaf(v.y, sc.y, sh.y), 0.f);
    v.z = fmaxf(fmaf(v.z, sc.z, sh.z), 0.f);
    v.w = fmaxf(fmaf(v.w, sc.w, sh.w), 0.f);
    out4[i] = v;
}

// ---------------- launch ----------------
extern "C" void kernel_launch(void* const* d_in, const int* in_sizes, int n_in,
                              void* d_out, int out_size) {
    const float* x     = (const float*)d_in[0];
    const int*   ei    = (const int*)  d_in[1];
    const float* eps   = (const float*)d_in[2];
    const float* W1    = (const float*)d_in[3];
    const float* b1    = (const float*)d_in[4];
    const float* g1    = (const float*)d_in[5];
    const float* beta1 = (const float*)d_in[6];
    const float* W2    = (const float*)d_in[7];
    const float* b2    = (const float*)d_in[8];
    const float* g2    = (const float*)d_in[9];
    const float* beta2 = (const float*)d_in[10];
    float* out = (float*)d_out;

    unsigned char *p_w1t, *p_w2t, *p_ahi, *p_alo, *p_h1hi, *p_h1lo;
    cudaGetSymbolAddress((void**)&p_w1t, g_w1t);
    cudaGetSymbolAddress((void**)&p_w2t, g_w2t);
    cudaGetSymbolAddress((void**)&p_ahi, g_ahi);
    cudaGetSymbolAddress((void**)&p_alo, g_alo);
    cudaGetSymbolAddress((void**)&p_h1hi, g_h1hi);
    cudaGetSymbolAddress((void**)&p_h1lo, g_h1lo);
    float *p_h1;  double *p_s1, *p_q1, *p_s2, *p_q2;
    cudaGetSymbolAddress((void**)&p_h1, g_h1);
    cudaGetSymbolAddress((void**)&p_s1, g_sum1);
    cudaGetSymbolAddress((void**)&p_q1, g_sq1);
    cudaGetSymbolAddress((void**)&p_s2, g_sum2);
    cudaGetSymbolAddress((void**)&p_q2, g_sq2);

    cudaFuncSetAttribute(gemm_k<4, 1, HID>,     cudaFuncAttributeMaxDynamicSharedMemorySize, SMEM_GEMM);
    cudaFuncSetAttribute(gemm_k<2, 2, OUT_DIM>, cudaFuncAttributeMaxDynamicSharedMemorySize, SMEM_GEMM);

    init_kernel<<<12500, 256>>>((const float4*)x, eps);
    prep_w_kernel<<<256, 256>>>(W1, W2);
    scatter_kernel<<<200000, 256>>>((const float4*)x, ei);
    split_aggr_kernel<<<12500, 256>>>();

    dim3 g1d(GRID_X, 2);   // persistent, 2 n-blocks of 128
    gemm_k<4, 1, HID><<<g1d, 256, SMEM_GEMM>>>(p_ahi, p_alo, p_w1t, b1, p_h1, p_s1, p_q1);
    stats1f_kernel<<<1, HID>>>(g1, beta1);
    split_h1_kernel<<<25000, 256>>>();

    dim3 g2d(GRID_X, 2);   // persistent, 2 n-halves of 64
    gemm_k<2, 2, OUT_DIM><<<g2d, 256, SMEM_GEMM>>>(p_h1hi, p_h1lo, p_w2t, b2, out, p_s2, p_q2);
    stats2f_kernel<<<1, OUT_DIM>>>(g2, beta2);

    final_kernel<<<12500, 256>>>((float4*)out);
}